// round 12
// baseline (speedup 1.0000x reference)
#include <cuda_runtime.h>
#include <cuda_bf16.h>
#include <math.h>
#include <stdint.h>

#define NB   512
#define SP   1024      // 32*32
#define FDIM 32768
#define HID  512
#define LAT  1024
#define NPF  ((float)(NB * SP))

// ---------------- scratch (device globals; no allocation allowed) -----------
__device__ float g_bufA[(size_t)NB * 64 * SP];       // 134 MB (both branches, 32ch)
__device__ float g_bufB[(size_t)2 * NB * 64 * SP];   // 268 MB (both branches, 64ch)
__device__ float g_hid [4 * NB * HID];               // FC1 out per combo
__device__ float g_cmu [NB * LAT];
__device__ float g_clv [NB * LAT];
__device__ float g_smu [NB * LAT];
__device__ float g_slv [NB * LAT];
__device__ float g_zc  [NB * LAT];
__device__ float g_zs  [NB * LAT];
__device__ float g_outc[NB * SP];
__device__ float g_outs[NB * SP];
__device__ float g_gmu [LAT];
__device__ float g_glv [LAT];
__device__ float g_accbuf[8 * 512 * 1024];   // 8 split-K accumulator slots (16 MB)
__device__ int   g_cnt[256];                 // ticket counters (FC1: 64, FC2: 128)
__device__ float g_statp[12 * 128];          // 12 BN slots: [c]{sum,sumsq}
__device__ float g_red [4];
__device__ float g_kl  [2];

// prepped conv weights, bf16 hi/lo, layout [inst][tap][oc][ICP]
#define WC2_PER (9 * 64 * 40)
#define WC3_PER (9 * 32 * 72)
__device__ __nv_bfloat16 g_wc2h[4 * WC2_PER];
__device__ __nv_bfloat16 g_wc2l[4 * WC2_PER];
__device__ __nv_bfloat16 g_wc3h[2 * WC3_PER];
__device__ __nv_bfloat16 g_wc3l[2 * WC3_PER];

__device__ __forceinline__ float lrelu(float v) { return v >= 0.f ? v : 0.01f * v; }

__device__ __forceinline__ uint32_t smem_u32(const void* p) {
    uint32_t a;
    asm("{ .reg .u64 t; cvta.to.shared.u64 t, %1; cvt.u32.u64 %0, t; }" : "=r"(a) : "l"(p));
    return a;
}

// ================= mma.sync bf16 primitives (sm_80+ baseline ISA) ============
__device__ __forceinline__ void ldm_x4(uint32_t* r, uint32_t addr) {
    asm volatile("ldmatrix.sync.aligned.m8n8.x4.shared.b16 {%0,%1,%2,%3}, [%4];"
        : "=r"(r[0]), "=r"(r[1]), "=r"(r[2]), "=r"(r[3]) : "r"(addr));
}
__device__ __forceinline__ void mma_bf16(float* c, const uint32_t* a, const uint32_t* b) {
    asm volatile("mma.sync.aligned.m16n8k16.row.col.f32.bf16.bf16.f32 "
        "{%0,%1,%2,%3}, {%4,%5,%6,%7}, {%8,%9}, {%0,%1,%2,%3};"
        : "+f"(c[0]), "+f"(c[1]), "+f"(c[2]), "+f"(c[3])
        : "r"(a[0]), "r"(a[1]), "r"(a[2]), "r"(a[3]), "r"(b[0]), "r"(b[1]));
}

__device__ __forceinline__ uint32_t pack_bf(__nv_bfloat16 a, __nv_bfloat16 b) {
    return (uint32_t)__bfloat16_as_ushort(a) | ((uint32_t)__bfloat16_as_ushort(b) << 16);
}

__device__ __forceinline__ void cvt_store2(__nv_bfloat16* hi, __nv_bfloat16* lo,
                                           int off, float4 a)
{
    __nv_bfloat16 h0 = __float2bfloat16(a.x), h1 = __float2bfloat16(a.y);
    __nv_bfloat16 h2 = __float2bfloat16(a.z), h3 = __float2bfloat16(a.w);
    __nv_bfloat16 l0 = __float2bfloat16(a.x - __bfloat162float(h0));
    __nv_bfloat16 l1 = __float2bfloat16(a.y - __bfloat162float(h1));
    __nv_bfloat16 l2 = __float2bfloat16(a.z - __bfloat162float(h2));
    __nv_bfloat16 l3 = __float2bfloat16(a.w - __bfloat162float(h3));
    *(uint2*)&hi[off] = make_uint2(pack_bf(h0, h1), pack_bf(h2, h3));
    *(uint2*)&lo[off] = make_uint2(pack_bf(l0, l1), pack_bf(l2, l3));
}

#define TSTR 40   // FC smem row stride (elems): 80B row cycles all banks

// ---------------- prep: conv weights -> bf16 hi/lo, padded [tap][oc][ICP] ----
__global__ __launch_bounds__(256)
void prep_convw_kernel(const float* __restrict__ encW2, const float* __restrict__ decW2,
                       const float* __restrict__ encW3)
{
    const int T2 = 4 * WC2_PER;
    for (int i = blockIdx.x * 256 + threadIdx.x; i < T2; i += gridDim.x * 256) {
        int icp = i % 40;
        int t = i / 40;
        int oc = t % 64; t /= 64;
        int tap = t % 9; int inst = t / 9;
        float v = 0.f;
        if (icp < 32) {
            const float* s = (inst < 2) ? encW2 : decW2;
            v = s[((((size_t)(inst & 1) * 64 + oc) * 32 + icp) * 9) + tap];
        }
        __nv_bfloat16 h = __float2bfloat16(v);
        g_wc2h[i] = h;
        g_wc2l[i] = __float2bfloat16(v - __bfloat162float(h));
    }
    const int T3 = 2 * WC3_PER;
    for (int i = blockIdx.x * 256 + threadIdx.x; i < T3; i += gridDim.x * 256) {
        int icp = i % 72;
        int t = i / 72;
        int oc = t % 32; t /= 32;
        int tap = t % 9; int br = t / 9;
        float v = 0.f;
        if (icp < 64)
            v = encW3[((((size_t)br * 32 + oc) * 64 + icp) * 9) + tap];
        __nv_bfloat16 h = __float2bfloat16(v);
        g_wc3h[i] = h;
        g_wc3l[i] = __float2bfloat16(v - __bfloat162float(h));
    }
}

// ---------------- mega zero ---------------------------------------------------
__global__ __launch_bounds__(256)
void mega_zero_kernel()
{
    for (int i = blockIdx.x * 256 + threadIdx.x; i < 8 * 512 * 1024; i += gridDim.x * 256) {
        g_accbuf[i] = 0.f;
        if (i < 12 * 128) g_statp[i] = 0.f;
        if (i < 256)      g_cnt[i] = 0;
        if (i < 4)        g_red[i] = 0.f;
    }
}

// ---------------- FC GEMM (merged combos): out = lrelu(A*B^T + bias) ---------
// grid (4, nTiles*4, splits). combo = by >> tShift selects {B,bias,out} and
// acc slot; A += (combo >> aShift) * aStride; statpIn (if set) indexed by
// branch = combo >> 1 with stride 384.
__global__ __launch_bounds__(256)
void fc_gemm_kernel(const float* __restrict__ A, size_t aStride, int aShift,
                    const float* __restrict__ B0, const float* __restrict__ B1,
                    const float* __restrict__ B2, const float* __restrict__ B3,
                    const float* __restrict__ bi0, const float* __restrict__ bi1,
                    const float* __restrict__ bi2, const float* __restrict__ bi3,
                    float* __restrict__ accBase, int* __restrict__ cnt,
                    float* __restrict__ o0, float* __restrict__ o1,
                    float* __restrict__ o2, float* __restrict__ o3,
                    int M, int Nn, int K, const float* __restrict__ statpB,
                    int tShift)
{
    __shared__ __nv_bfloat16 sAhi[128 * TSTR], sAlo[128 * TSTR];
    __shared__ __nv_bfloat16 sBhi[128 * TSTR], sBlo[128 * TSTR];
    __shared__ float sstat[64];
    __shared__ int lastFlag;

    const int tid = threadIdx.x;
    const int wid = tid >> 5, lane = tid & 31;
    const int wm = (wid >> 2) * 64;
    const int wn = (wid & 3) * 32;

    const int combo = blockIdx.y >> tShift;
    const int ny = blockIdx.y & ((1 << tShift) - 1);
    const int m0 = blockIdx.x * 128, n0 = ny * 128;
    const int kChunk = K / gridDim.z;
    const int k0 = blockIdx.z * kChunk;

    const float* Aq = A + (size_t)(combo >> aShift) * aStride;
    const float* B  = combo == 0 ? B0 : combo == 1 ? B1 : combo == 2 ? B2 : B3;
    const float* bias = combo == 0 ? bi0 : combo == 1 ? bi1 : combo == 2 ? bi2 : bi3;
    float* outBuf = combo == 0 ? o0 : combo == 1 ? o1 : combo == 2 ? o2 : o3;
    float* acc = accBase + (size_t)combo * (512 * 1024);
    const float* statpIn = statpB ? statpB + (combo >> 1) * 384 : nullptr;

    if (statpIn && tid < 32) {
        float m = statpIn[tid * 2] / NPF;
        float var = statpIn[tid * 2 + 1] / NPF - m * m;
        sstat[tid * 2] = m;
        sstat[tid * 2 + 1] = rsqrtf(var + 1e-5f);
    }
    __syncthreads();

    const uint32_t aHi = smem_u32(sAhi), aLo = smem_u32(sAlo);
    const uint32_t bHi = smem_u32(sBhi), bLo = smem_u32(sBlo);

    const uint32_t aRow = (uint32_t)(lane & 15);
    const uint32_t aColB = (uint32_t)((lane >> 4) * 16);
    const uint32_t bRow = (uint32_t)((lane & 7) + ((lane >> 4) & 1) * 8);
    const uint32_t bColB = (uint32_t)(((lane >> 3) & 1) * 16);

    float accr[4][4][4];
#pragma unroll
    for (int i = 0; i < 4; i++)
#pragma unroll
        for (int j = 0; j < 4; j++)
#pragma unroll
            for (int r = 0; r < 4; r++) accr[i][j][r] = 0.f;

    for (int kb = k0; kb < k0 + kChunk; kb += 32) {
        for (int idx = tid; idx < 1024; idx += 256) {
            int r = idx >> 3;
            int c = (idx & 7) << 2;
            float4 va = *(const float4*)&Aq[(size_t)(m0 + r) * K + kb + c];
            if (statpIn) {
                int ch = (kb + c) >> 10;
                float m = sstat[ch * 2], iv = sstat[ch * 2 + 1];
                va.x = lrelu((va.x - m) * iv);
                va.y = lrelu((va.y - m) * iv);
                va.z = lrelu((va.z - m) * iv);
                va.w = lrelu((va.w - m) * iv);
            }
            cvt_store2(sAhi, sAlo, r * TSTR + c, va);
            float4 vb = *(const float4*)&B[(size_t)(n0 + r) * K + kb + c];
            cvt_store2(sBhi, sBlo, r * TSTR + c, vb);
        }
        __syncthreads();

#pragma unroll
        for (int s = 0; s < 2; s++) {
            const uint32_t kofB = s * 32;
            uint32_t afh[4][4], afl[4][4];
#pragma unroll
            for (int mf = 0; mf < 4; mf++) {
                uint32_t off = (uint32_t)(wm + mf * 16 + aRow) * (TSTR * 2) + kofB + aColB;
                ldm_x4(afh[mf], aHi + off);
                ldm_x4(afl[mf], aLo + off);
            }
            uint32_t bfh[2][4], bfl[2][4];
#pragma unroll
            for (int h = 0; h < 2; h++) {
                uint32_t off = (uint32_t)(wn + h * 16 + bRow) * (TSTR * 2) + kofB + bColB;
                ldm_x4(bfh[h], bHi + off);
                ldm_x4(bfl[h], bLo + off);
            }
#pragma unroll
            for (int mf = 0; mf < 4; mf++)
#pragma unroll
                for (int nf = 0; nf < 4; nf++) {
                    const uint32_t* ph = &bfh[nf >> 1][(nf & 1) * 2];
                    const uint32_t* pl = &bfl[nf >> 1][(nf & 1) * 2];
                    mma_bf16(accr[mf][nf], afh[mf], ph);
                    mma_bf16(accr[mf][nf], afh[mf], pl);
                    mma_bf16(accr[mf][nf], afl[mf], ph);
                }
        }
        __syncthreads();
    }

    const int rbase = m0 + wm + (lane >> 2);
    const int cbase = n0 + wn + (lane & 3) * 2;
#pragma unroll
    for (int mf = 0; mf < 4; mf++)
#pragma unroll
        for (int nf = 0; nf < 4; nf++) {
            int row = rbase + mf * 16;
            int col = cbase + nf * 8;
            atomicAdd(&acc[(size_t)row * Nn + col],           accr[mf][nf][0]);
            atomicAdd(&acc[(size_t)row * Nn + col + 1],       accr[mf][nf][1]);
            atomicAdd(&acc[(size_t)(row + 8) * Nn + col],     accr[mf][nf][2]);
            atomicAdd(&acc[(size_t)(row + 8) * Nn + col + 1], accr[mf][nf][3]);
        }

    __threadfence();
    if (tid == 0) {
        int old = atomicAdd(&cnt[blockIdx.x * gridDim.y + blockIdx.y], 1);
        lastFlag = (old == (int)gridDim.z - 1);
    }
    __syncthreads();
    if (lastFlag) {
        __threadfence();
        const int r = tid >> 1;
        const int cb = (tid & 1) * 64;
#pragma unroll
        for (int j = 0; j < 16; j++) {
            int col = cb + j * 4;
            float4 v = *(const float4*)&acc[(size_t)(m0 + r) * Nn + n0 + col];
            float4 b = *(const float4*)&bias[n0 + col];
            v.x = lrelu(v.x + b.x); v.y = lrelu(v.y + b.y);
            v.z = lrelu(v.z + b.z); v.w = lrelu(v.w + b.w);
            *(float4*)&outBuf[(size_t)(m0 + r) * Nn + n0 + col] = v;
        }
    }
}

// ---------------- implicit-GEMM conv 3x3 SAME (bf16 hi/lo), branch-merged ----
// grid (NB*8, 2): blockIdx.y = branch; all per-branch offsets via strides.
template<int IC, int OC>
__global__ __launch_bounds__(256, OC == 64 ? 4 : 3)
void conv_mma_kernel(const float* __restrict__ in, size_t inStride,
                     const __nv_bfloat16* __restrict__ wHi,
                     const __nv_bfloat16* __restrict__ wLo, int wStride,
                     const float* __restrict__ bias, int biasStride,
                     const float* __restrict__ statpIn, float* __restrict__ statpOut,
                     float* __restrict__ out, size_t outStride)
{
    constexpr int ICP = (IC == 32) ? 40 : 72;
    constexpr int ISZ = 6 * 34 * ICP;
    constexpr int WSZ = OC * ICP;
    constexpr int KSTEPS = IC / 16;
    constexpr int LOG2IC = (IC == 32) ? 5 : 6;
    constexpr int WARPS_M = (OC == 64) ? 4 : 8;
    constexpr int WM = 128 / WARPS_M;
    constexpr int MFRAG = WM / 16;
    constexpr int NFRAG = 4;

    extern __shared__ char smraw[];
    __nv_bfloat16* sIhi = (__nv_bfloat16*)smraw;
    __nv_bfloat16* sIlo = sIhi + ISZ;
    __nv_bfloat16* sWh  = sIlo + ISZ;
    __nv_bfloat16* sWl  = sWh + WSZ;
    float* sstatIn  = (float*)(sWl + WSZ);
    float* sstatOut = sstatIn + 2 * IC;

    const int br = blockIdx.y;
    const float* inq = in + (size_t)br * inStride;
    const __nv_bfloat16* wHiq = wHi + (size_t)br * wStride;
    const __nv_bfloat16* wLoq = wLo + (size_t)br * wStride;
    const float* biasq = bias + br * biasStride;
    const float* sIn = statpIn + br * 384;
    float* sOut = statpOut + br * 384;
    float* outq = out + (size_t)br * outStride;

    const int tid  = threadIdx.x;
    const int wid  = tid >> 5, lane = tid & 31;
    const int n    = blockIdx.x >> 3;
    const int tile = blockIdx.x & 7;
    const int r0   = tile * 4;

    if (tid < IC) {
        float m = sIn[tid * 2] / NPF;
        float var = sIn[tid * 2 + 1] / NPF - m * m;
        sstatIn[tid * 2] = m;
        sstatIn[tid * 2 + 1] = rsqrtf(var + 1e-5f);
    }
    for (int i = tid; i < 2 * OC; i += 256) sstatOut[i] = 0.f;
    __syncthreads();

    const float* src = inq + (size_t)n * IC * SP;
    for (int i = tid; i < 6 * 34 * IC; i += 256) {
        int c = i % 34;
        int rest = i / 34;
        int ic = rest & (IC - 1);
        int r = rest >> LOG2IC;
        int row = r0 - 1 + r, col = c - 1;
        float v = 0.f;
        if ((unsigned)row < 32u && (unsigned)col < 32u) {
            v = src[(size_t)ic * SP + row * 32 + col];
            v = (v - sstatIn[ic * 2]) * sstatIn[ic * 2 + 1];
            v = v >= 0.f ? v : 0.01f * v;
        }
        __nv_bfloat16 h = __float2bfloat16(v);
        int o = (r * 34 + c) * ICP + ic;
        sIhi[o] = h;
        sIlo[o] = __float2bfloat16(v - __bfloat162float(h));
    }

    const int wm = (OC == 64) ? ((wid >> 1) * 32) : (wid * 16);
    const int wn = (OC == 64) ? ((wid & 1) * 32) : 0;

    uint32_t aBase[MFRAG];
    {
        int pixl = wm + (lane & 15);
#pragma unroll
        for (int mf = 0; mf < MFRAG; mf++) {
            int p = pixl + mf * 16;
            int plane = (p >> 5) * 34 + (p & 31);
            aBase[mf] = (uint32_t)(plane * ICP * 2) + ((lane & 16) ? 16u : 0u);
        }
    }
    const uint32_t aHiB = smem_u32(sIhi), aLoB = smem_u32(sIlo);
    const uint32_t wHiB = smem_u32(sWh),  wLoB = smem_u32(sWl);
    const uint32_t bRow  = (uint32_t)((lane & 7) + ((lane >> 4) & 1) * 8);
    const uint32_t bColB = (uint32_t)((((lane >> 3) & 1) * 8) * 2);

    float acc[MFRAG][NFRAG][4];
#pragma unroll
    for (int mf = 0; mf < MFRAG; mf++)
#pragma unroll
        for (int nf = 0; nf < NFRAG; nf++) {
            float b0 = biasq[wn + nf * 8 + (lane & 3) * 2];
            float b1 = biasq[wn + nf * 8 + (lane & 3) * 2 + 1];
            acc[mf][nf][0] = b0; acc[mf][nf][1] = b1;
            acc[mf][nf][2] = b0; acc[mf][nf][3] = b1;
        }

    for (int tap = 0; tap < 9; tap++) {
        __syncthreads();
        {
            const uint4* gh = (const uint4*)(wHiq + tap * WSZ);
            const uint4* gl = (const uint4*)(wLoq + tap * WSZ);
            uint4* dh = (uint4*)sWh;
            uint4* dl = (uint4*)sWl;
            for (int i = tid; i < WSZ / 8; i += 256) { dh[i] = gh[i]; dl[i] = gl[i]; }
        }
        __syncthreads();

        const uint32_t tapOff = (uint32_t)((((tap / 3) * 34) + (tap % 3)) * ICP * 2);
#pragma unroll
        for (int ks = 0; ks < KSTEPS; ks++) {
            const uint32_t kOff = (uint32_t)(ks * 32);
            uint32_t afh[MFRAG][4], afl[MFRAG][4];
#pragma unroll
            for (int mf = 0; mf < MFRAG; mf++) {
                uint32_t ad = aBase[mf] + tapOff + kOff;
                ldm_x4(afh[mf], aHiB + ad);
                ldm_x4(afl[mf], aLoB + ad);
            }
            uint32_t bfh[2][4], bfl[2][4];
#pragma unroll
            for (int h = 0; h < 2; h++) {
                uint32_t od = (uint32_t)((wn + h * 16 + bRow) * ICP) * 2 + kOff + bColB;
                ldm_x4(bfh[h], wHiB + od);
                ldm_x4(bfl[h], wLoB + od);
            }
#pragma unroll
            for (int mf = 0; mf < MFRAG; mf++)
#pragma unroll
                for (int nf = 0; nf < NFRAG; nf++) {
                    const uint32_t* ph = &bfh[nf >> 1][(nf & 1) * 2];
                    const uint32_t* pl = &bfl[nf >> 1][(nf & 1) * 2];
                    mma_bf16(acc[mf][nf], afh[mf], ph);
                    mma_bf16(acc[mf][nf], afh[mf], pl);
                    mma_bf16(acc[mf][nf], afl[mf], ph);
                }
        }
    }

#pragma unroll
    for (int nf = 0; nf < NFRAG; nf++) {
        float s0 = 0.f, q0 = 0.f, s1 = 0.f, q1 = 0.f;
#pragma unroll
        for (int mf = 0; mf < MFRAG; mf++) {
            float v0 = acc[mf][nf][0], v1 = acc[mf][nf][1];
            float v2 = acc[mf][nf][2], v3 = acc[mf][nf][3];
            s0 += v0 + v2; q0 += v0 * v0 + v2 * v2;
            s1 += v1 + v3; q1 += v1 * v1 + v3 * v3;
        }
#pragma unroll
        for (int off = 4; off < 32; off <<= 1) {
            s0 += __shfl_xor_sync(~0u, s0, off);
            q0 += __shfl_xor_sync(~0u, q0, off);
            s1 += __shfl_xor_sync(~0u, s1, off);
            q1 += __shfl_xor_sync(~0u, q1, off);
        }
        if (lane < 4) {
            int c0 = wn + nf * 8 + lane * 2;
            atomicAdd(&sstatOut[c0 * 2],     s0);
            atomicAdd(&sstatOut[c0 * 2 + 1], q0);
            atomicAdd(&sstatOut[(c0 + 1) * 2],     s1);
            atomicAdd(&sstatOut[(c0 + 1) * 2 + 1], q1);
        }
    }

    float* dst = outq + (size_t)n * OC * SP + tile * 128;
    const int prow  = lane >> 2;
    const int pcol0 = (lane & 3) * 2;
#pragma unroll
    for (int mf = 0; mf < MFRAG; mf++)
#pragma unroll
        for (int nf = 0; nf < NFRAG; nf++) {
            int p0 = wm + mf * 16 + prow;
            int oc = wn + nf * 8 + pcol0;
            dst[(size_t)oc * SP + p0]           = acc[mf][nf][0];
            dst[(size_t)(oc + 1) * SP + p0]     = acc[mf][nf][1];
            dst[(size_t)oc * SP + p0 + 8]       = acc[mf][nf][2];
            dst[(size_t)(oc + 1) * SP + p0 + 8] = acc[mf][nf][3];
        }

    __syncthreads();
    for (int i = tid; i < 2 * OC; i += 256)
        atomicAdd(&sOut[i], sstatOut[i]);
}

// ---------------- direct conv 1->32, branch-merged (grid NB x 4 x 2) ---------
__global__ __launch_bounds__(256)
void conv1_kernel(const float* __restrict__ in0, const float* __restrict__ in1,
                  const float* __restrict__ w, const float* __restrict__ bias,
                  float* __restrict__ statpOut, float* __restrict__ out)
{
    constexpr int OCT = 8;
    __shared__ __align__(16) float ws[9 * OCT];
    __shared__ float plane[34 * 35];
    __shared__ float so[2 * OCT];
    const int tid = threadIdx.x;
    const int n   = blockIdx.x;
    const int ocb = blockIdx.y * OCT;
    const int br  = blockIdx.z;

    const float* inq = br ? in1 : in0;
    const float* wq = w + br * 32 * 9;
    const float* biasq = bias + br * 32;
    float* sOut = statpOut + br * 384;
    float* outq = out + (size_t)br * NB * 32 * SP;

    if (tid < 2 * OCT) so[tid] = 0.f;
    for (int idx = tid; idx < 9 * OCT; idx += 256) {
        int oc = idx % OCT, t = idx / OCT;
        ws[idx] = wq[(size_t)(ocb + oc) * 9 + t];
    }

    const float* s = inq + (size_t)n * SP;
    for (int p = tid; p < 34 * 34; p += 256) {
        int py = p / 34 - 1, px = p % 34 - 1;
        float v = 0.f;
        if ((unsigned)py < 32u && (unsigned)px < 32u) v = s[py * 32 + px];
        plane[(p / 34) * 35 + (p % 34)] = v;
    }

    float acc[OCT][4];
#pragma unroll
    for (int oc = 0; oc < OCT; oc++) {
        float b = biasq[ocb + oc];
#pragma unroll
        for (int p = 0; p < 4; p++) acc[oc][p] = b;
    }

    const int row  = tid >> 3;
    const int col0 = (tid & 7) * 4;
    __syncthreads();

    float v[3][6];
#pragma unroll
    for (int dy = 0; dy < 3; dy++)
#pragma unroll
        for (int dx = 0; dx < 6; dx++)
            v[dy][dx] = plane[(row + dy) * 35 + col0 + dx];

#pragma unroll
    for (int t = 0; t < 9; t++) {
        const int ky = t / 3, kx = t % 3;
        float4 w0 = *(const float4*)&ws[t * 8];
        float4 w1 = *(const float4*)&ws[t * 8 + 4];
#pragma unroll
        for (int p = 0; p < 4; p++) {
            float vv = v[ky][kx + p];
            acc[0][p] += vv * w0.x; acc[1][p] += vv * w0.y;
            acc[2][p] += vv * w0.z; acc[3][p] += vv * w0.w;
            acc[4][p] += vv * w1.x; acc[5][p] += vv * w1.y;
            acc[6][p] += vv * w1.z; acc[7][p] += vv * w1.w;
        }
    }

#pragma unroll
    for (int oc = 0; oc < OCT; oc++) {
        float4 o = make_float4(acc[oc][0], acc[oc][1], acc[oc][2], acc[oc][3]);
        *(float4*)&outq[((size_t)n * 32 + ocb + oc) * SP + row * 32 + col0] = o;
        float sm = acc[oc][0] + acc[oc][1] + acc[oc][2] + acc[oc][3];
        float q = acc[oc][0] * acc[oc][0] + acc[oc][1] * acc[oc][1]
                + acc[oc][2] * acc[oc][2] + acc[oc][3] * acc[oc][3];
#pragma unroll
        for (int off = 16; off > 0; off >>= 1) {
            sm += __shfl_xor_sync(~0u, sm, off);
            q  += __shfl_xor_sync(~0u, q, off);
        }
        if ((tid & 31) == 0) {
            atomicAdd(&so[oc * 2], sm);
            atomicAdd(&so[oc * 2 + 1], q);
        }
    }
    __syncthreads();
    if (tid < 2 * OCT)
        atomicAdd(&sOut[ocb * 2 + tid], so[tid]);
}

// ---------------- decoder final conv 64->1, branch-merged (NB x 8 x 2) -------
__global__ __launch_bounds__(256)
void dec3_kernel(const float* __restrict__ in, const float* __restrict__ w,
                 const float* __restrict__ bias,
                 const float* __restrict__ statpIn, float* __restrict__ statpOut,
                 float* __restrict__ out0, float* __restrict__ out1)
{
    __shared__ float sw[64 * 9];
    __shared__ float halo[2][6 * 35];
    __shared__ float sstatIn[128];
    __shared__ float so[2];

    const int tid  = threadIdx.x;
    const int n    = blockIdx.x;
    const int tile = blockIdx.y;
    const int br   = blockIdx.z;
    const int r0   = tile * 4;
    const int pixel = tid >> 1;
    const int half  = tid & 1;
    const int prow  = pixel >> 5;
    const int pcol  = pixel & 31;

    const float* inq = in + (size_t)br * NB * 64 * SP;
    const float* wq = w + br * 64 * 9;
    const float* sIn = statpIn + br * 384;
    float* sOut = statpOut + br * 384;
    float* outq = br ? out1 : out0;

    if (tid < 64) {
        float m = sIn[tid * 2] / NPF;
        float var = sIn[tid * 2 + 1] / NPF - m * m;
        sstatIn[tid * 2] = m;
        sstatIn[tid * 2 + 1] = rsqrtf(var + 1e-5f);
    }
    if (tid < 2) so[tid] = 0.f;
    for (int i = tid; i < 64 * 9; i += 256) sw[i] = wq[i];

    const float* src = inq + (size_t)n * 64 * SP;

    auto loadHalo = [&](int ic) {
        float m = sstatIn[ic * 2], iv = sstatIn[ic * 2 + 1];
        const float* s = src + (size_t)ic * SP;
        float* d = halo[ic & 1];
        for (int p = tid; p < 6 * 34; p += 256) {
            int r = p / 34, c = p % 34;
            int row = r0 - 1 + r, col = c - 1;
            float v = 0.f;
            if ((unsigned)row < 32u && (unsigned)col < 32u) {
                v = s[row * 32 + col];
                v = (v - m) * iv;
                v = v >= 0.f ? v : 0.01f * v;
            }
            d[r * 35 + c] = v;
        }
    };

    __syncthreads();
    loadHalo(0);
    __syncthreads();

    float acc = 0.f;
    for (int ic = 0; ic < 64; ic++) {
        if (ic + 1 < 64) loadHalo(ic + 1);
        if ((ic >> 5) == half) {
            const float* pl = halo[ic & 1];
            const float* wp = &sw[ic * 9];
#pragma unroll
            for (int t = 0; t < 9; t++)
                acc += pl[(prow + t / 3) * 35 + pcol + t % 3] * wp[t];
        }
        __syncthreads();
    }

    float other = __shfl_xor_sync(~0u, acc, 1);
    float v = acc + other + bias[br];
    if (half == 0)
        outq[(size_t)n * SP + tile * 128 + pixel] = v;

    float s = (half == 0) ? v : 0.f;
    float q = (half == 0) ? v * v : 0.f;
#pragma unroll
    for (int off = 16; off > 0; off >>= 1) {
        s += __shfl_xor_sync(~0u, s, off);
        q += __shfl_xor_sync(~0u, q, off);
    }
    if ((tid & 31) == 0) {
        atomicAdd(&so[0], s);
        atomicAdd(&so[1], q);
    }
    __syncthreads();
    if (tid < 2)
        atomicAdd(&sOut[tid], so[tid]);
}

// ---------------- PoE (parallel: 8 threads per latent) -----------------------
__global__ __launch_bounds__(256)
void poe_kernel(const float* __restrict__ smu, const float* __restrict__ slv,
                float* __restrict__ gmu, float* __restrict__ glv)
{
    const int tid = threadIdx.x;
    const int l   = blockIdx.x * 32 + (tid >> 3);
    const int sub = tid & 7;
    float s1 = 0.f, s2 = 0.f;
    for (int n = sub * 64; n < (sub + 1) * 64; n++) {
        float lv = slv[n * LAT + l];
        float pr = expf(-lv);
        s1 += pr;
        s2 += smu[n * LAT + l] * pr;
    }
#pragma unroll
    for (int off = 4; off > 0; off >>= 1) {
        s1 += __shfl_xor_sync(~0u, s1, off);
        s2 += __shfl_xor_sync(~0u, s2, off);
    }
    if (sub == 0) {
        float gv = 1.f / s1;
        gmu[l] = s2 * gv;
        glv[l] = logf(gv);
    }
}

__global__ void reparam_c_kernel(const float* __restrict__ eps, const float* __restrict__ lv,
                                 const float* __restrict__ mu, float* __restrict__ z)
{
    int i = blockIdx.x * 256 + threadIdx.x;
    if (i >= NB * LAT) return;
    z[i] = eps[i] * expf(0.5f * lv[i]) + mu[i];
}

__global__ void reparam_s_kernel(const float* __restrict__ eps, const float* __restrict__ glv,
                                 const float* __restrict__ gmu, float* __restrict__ z)
{
    int i = blockIdx.x * 256 + threadIdx.x;
    if (i >= NB * LAT) return;
    int l = i & (LAT - 1);
    z[i] = eps[i] * expf(0.5f * glv[l]) + gmu[l];
}

// ---------------- KL reductions ----------------------------------------------
__global__ __launch_bounds__(256)
void kl_class_kernel(const float* __restrict__ mu, const float* __restrict__ lv,
                     float* __restrict__ red)
{
    float a = 0.f, b = 0.f, c = 0.f;
    for (int i = blockIdx.x * 256 + threadIdx.x; i < NB * LAT; i += gridDim.x * 256) {
        float l = lv[i], m = mu[i];
        a += 1.f + l;
        b += m * m;
        c += expf(2.f * l);
    }
    __shared__ float sh0[256], sh1[256], sh2[256];
    int tid = threadIdx.x;
    sh0[tid] = a; sh1[tid] = b; sh2[tid] = c;
    __syncthreads();
    for (int o = 128; o > 0; o >>= 1) {
        if (tid < o) { sh0[tid] += sh0[tid + o]; sh1[tid] += sh1[tid + o]; sh2[tid] += sh2[tid + o]; }
        __syncthreads();
    }
    if (tid == 0) {
        atomicAdd(&red[0], sh0[0]);
        atomicAdd(&red[1], sh1[0]);
        atomicAdd(&red[2], sh2[0]);
    }
}

__global__ __launch_bounds__(256)
void kl_final_kernel(const float* __restrict__ gmu, const float* __restrict__ glv,
                     const float* __restrict__ red, float* __restrict__ kl)
{
    float a = 0.f, b = 0.f, c = 0.f;
    int tid = threadIdx.x;
    for (int l = tid; l < LAT; l += 256) {
        float g = glv[l], m = gmu[l];
        a += 1.f + g;
        b += m * m;
        c += expf(2.f * g);
    }
    __shared__ float sh0[256], sh1[256], sh2[256];
    sh0[tid] = a; sh1[tid] = b; sh2[tid] = c;
    __syncthreads();
    for (int o = 128; o > 0; o >>= 1) {
        if (tid < o) { sh0[tid] += sh0[tid + o]; sh1[tid] += sh1[tid + o]; sh2[tid] += sh2[tid + o]; }
        __syncthreads();
    }
    if (tid == 0) {
        kl[0] = -0.5f * red[0] + 0.5f * (red[1] + red[2]);
        kl[1] = -0.5f * sh0[0] + 0.5f * (sh1[0] + sh2[0]);
    }
}

// ---------------- final loss + output (applies decoder-final BNs) ------------
__global__ __launch_bounds__(256)
void final_kernel(const float* __restrict__ x, const float* __restrict__ outc,
                  const float* __restrict__ outs, const float* __restrict__ kl,
                  const float* __restrict__ spC, const float* __restrict__ spS,
                  float* __restrict__ dout)
{
    int i = blockIdx.x * 256 + threadIdx.x;
    if (i >= NB * SP) return;
    float mc = spC[0] / NPF, vc = spC[1] / NPF - mc * mc;
    float ivc = rsqrtf(vc + 1e-5f);
    float ms = spS[0] / NPF, vs = spS[1] / NPF - ms * ms;
    float ivs = rsqrtf(vs + 1e-5f);
    float oc = lrelu((outc[i] - mc) * ivc);
    float os = fmaxf((outs[i] - ms) * ivs, 0.f);
    float o  = oc * os;
    float d  = expf(x[i]) - expf(o);
    dout[i]           = -kl[0] + kl[1] + d * d;
    dout[NB * SP + i] = o;
}

// ---------------- host orchestration -----------------------------------------
#define SMEM_C2 ((2 * 8160 + 2 * 2560) * 2 + (2 * 32 + 2 * 64) * 4)    // 43648
#define SMEM_C3 ((2 * 14688 + 2 * 2304) * 2 + (2 * 64 + 2 * 32) * 4)   // 68736

extern "C" void kernel_launch(void* const* d_in, const int* in_sizes, int n_in,
                              void* d_out, int out_size)
{
    (void)in_sizes; (void)n_in; (void)out_size;

    const float* x       = (const float*)d_in[0];
    const float* eps_c   = (const float*)d_in[1];
    const float* eps_s   = (const float*)d_in[2];
    const float* enc_cw1 = (const float*)d_in[3];
    const float* enc_cb1 = (const float*)d_in[4];
    const float* enc_cw2 = (const float*)d_in[5];
    const float* enc_cb2 = (const float*)d_in[6];
    const float* enc_cw3 = (const float*)d_in[7];
    const float* enc_cb3 = (const float*)d_in[8];
    const float* enc_muW1 = (const float*)d_in[9];
    const float* enc_muB1 = (const float*)d_in[10];
    const float* enc_muW2 = (const float*)d_in[11];
    const float* enc_muB2 = (const float*)d_in[12];
    const float* enc_vaW1 = (const float*)d_in[13];
    const float* enc_vaB1 = (const float*)d_in[14];
    const float* enc_vaW2 = (const float*)d_in[15];
    const float* enc_vaB2 = (const float*)d_in[16];
    const float* dec_cw1 = (const float*)d_in[17];
    const float* dec_cb1 = (const float*)d_in[18];
    const float* dec_cw2 = (const float*)d_in[19];
    const float* dec_cb2 = (const float*)d_in[20];
    const float* dec_cw3 = (const float*)d_in[21];
    const float* dec_cb3 = (const float*)d_in[22];

    cudaFuncSetAttribute(conv_mma_kernel<32, 64>,
                         cudaFuncAttributeMaxDynamicSharedMemorySize, SMEM_C2);
    cudaFuncSetAttribute(conv_mma_kernel<64, 32>,
                         cudaFuncAttributeMaxDynamicSharedMemorySize, SMEM_C3);

    float *bufA, *bufB, *hid, *cmu, *clv, *smu, *slv, *zc, *zs;
    float *outc, *outs, *gmu, *glv, *statp, *accb, *red, *kl;
    int* cnt;
    __nv_bfloat16 *wc2h, *wc2l, *wc3h, *wc3l;
    cudaGetSymbolAddress((void**)&bufA,  g_bufA);
    cudaGetSymbolAddress((void**)&bufB,  g_bufB);
    cudaGetSymbolAddress((void**)&hid,   g_hid);
    cudaGetSymbolAddress((void**)&cmu,   g_cmu);
    cudaGetSymbolAddress((void**)&clv,   g_clv);
    cudaGetSymbolAddress((void**)&smu,   g_smu);
    cudaGetSymbolAddress((void**)&slv,   g_slv);
    cudaGetSymbolAddress((void**)&zc,    g_zc);
    cudaGetSymbolAddress((void**)&zs,    g_zs);
    cudaGetSymbolAddress((void**)&outc,  g_outc);
    cudaGetSymbolAddress((void**)&outs,  g_outs);
    cudaGetSymbolAddress((void**)&gmu,   g_gmu);
    cudaGetSymbolAddress((void**)&glv,   g_glv);
    cudaGetSymbolAddress((void**)&statp, g_statp);
    cudaGetSymbolAddress((void**)&accb,  g_accbuf);
    cudaGetSymbolAddress((void**)&cnt,   g_cnt);
    cudaGetSymbolAddress((void**)&red,   g_red);
    cudaGetSymbolAddress((void**)&kl,    g_kl);
    cudaGetSymbolAddress((void**)&wc2h,  g_wc2h);
    cudaGetSymbolAddress((void**)&wc2l,  g_wc2l);
    cudaGetSymbolAddress((void**)&wc3h,  g_wc3h);
    cudaGetSymbolAddress((void**)&wc3l,  g_wc3l);

    const size_t s32 = (size_t)NB * 32 * SP;   // per-branch 32ch tensor
    const size_t s64 = (size_t)NB * 64 * SP;   // per-branch 64ch tensor
    const size_t HF  = (size_t)HID * FDIM;
    const size_t LH  = (size_t)LAT * HID;

    mega_zero_kernel<<<2048, 256>>>();
    prep_convw_kernel<<<256, 256>>>(enc_cw2, dec_cw2, enc_cw3);

    // ---- encode (both branches merged) ----
    conv1_kernel<<<dim3(NB, 4, 2), 256>>>(x, x, enc_cw1, enc_cb1, statp, bufA);
    conv_mma_kernel<32, 64><<<dim3(NB * 8, 2), 256, SMEM_C2>>>(
        bufA, s32, wc2h, wc2l, WC2_PER, enc_cb2, 64,
        statp, statp + 128, bufB, s64);
    conv_mma_kernel<64, 32><<<dim3(NB * 8, 2), 256, SMEM_C3>>>(
        bufB, s64, wc3h, wc3l, WC3_PER, enc_cb3, 32,
        statp + 128, statp + 256, bufA, s32);

    // FC1: combos {br0mu, br0va, br1mu, br1va}
    fc_gemm_kernel<<<dim3(4, 16, 16), 256>>>(
        bufA, (size_t)NB * FDIM, 1,
        enc_muW1, enc_vaW1, enc_muW1 + HF, enc_vaW1 + HF,
        enc_muB1, enc_vaB1, enc_muB1 + HID, enc_vaB1 + HID,
        accb, cnt,
        hid, hid + NB * HID, hid + 2 * NB * HID, hid + 3 * NB * HID,
        NB, HID, FDIM, statp + 256, 2);
    // FC2
    fc_gemm_kernel<<<dim3(4, 32, 4), 256>>>(
        hid, (size_t)NB * HID, 0,
        enc_muW2, enc_vaW2, enc_muW2 + LH, enc_vaW2 + LH,
        enc_muB2, enc_vaB2, enc_muB2 + LAT, enc_vaB2 + LAT,
        accb + (size_t)4 * 512 * 1024, cnt + 128,
        cmu, clv, smu, slv,
        NB, LAT, HID, nullptr, 3);

    // ---- PoE + reparameterize ----
    poe_kernel<<<32, 256>>>(smu, slv, gmu, glv);
    reparam_c_kernel<<<(NB * LAT) / 256, 256>>>(eps_c, clv, cmu, zc);
    reparam_s_kernel<<<(NB * LAT) / 256, 256>>>(eps_s, glv, gmu, zs);

    // ---- decode (both branches merged) ----
    conv1_kernel<<<dim3(NB, 4, 2), 256>>>(zc, zs, dec_cw1, dec_cb1, statp + 6 * 128, bufA);
    conv_mma_kernel<32, 64><<<dim3(NB * 8, 2), 256, SMEM_C2>>>(
        bufA, s32, wc2h + 2 * WC2_PER, wc2l + 2 * WC2_PER, WC2_PER, dec_cb2, 64,
        statp + 6 * 128, statp + 7 * 128, bufB, s64);
    dec3_kernel<<<dim3(NB, 8, 2), 256>>>(
        bufB, dec_cw3, dec_cb3, statp + 7 * 128, statp + 8 * 128, outc, outs);

    // ---- KL + final ----
    kl_class_kernel<<<256, 256>>>(cmu, clv, red);
    kl_final_kernel<<<1, 256>>>(gmu, glv, red, kl);
    final_kernel<<<(NB * SP) / 256, 256>>>(x, outc, outs, kl,
                                           statp + 8 * 128, statp + 11 * 128,
                                           (float*)d_out);
}

// round 13
// speedup vs baseline: 1.4460x; 1.4460x over previous
#include <cuda_runtime.h>
#include <cuda_bf16.h>
#include <math.h>
#include <stdint.h>

#define NB   512
#define SP   1024      // 32*32
#define FDIM 32768
#define HID  512
#define LAT  1024
#define NPF  ((float)(NB * SP))

// ---------------- scratch (device globals; no allocation allowed) -----------
__device__ float g_bufA[(size_t)NB * 64 * SP];   // 134 MB
__device__ float g_bufB[(size_t)NB * 64 * SP];   // 134 MB
__device__ float g_hid [NB * HID];
__device__ float g_cmu [NB * LAT];
__device__ float g_clv [NB * LAT];
__device__ float g_smu [NB * LAT];
__device__ float g_slv [NB * LAT];
__device__ float g_zc  [NB * LAT];
__device__ float g_zs  [NB * LAT];
__device__ float g_outc[NB * SP];
__device__ float g_outs[NB * SP];
__device__ float g_gmu [LAT];
__device__ float g_glv [LAT];
__device__ float g_accbuf[8 * 512 * 1024];   // 8 split-K accumulator slots (16 MB)
__device__ int   g_cnt[8 * 64];              // 8 ticket-counter slots
__device__ float g_statp[12 * 128];          // 12 BN slots: [c]{sum,sumsq}
__device__ float g_red [4];
__device__ float g_kl  [2];

// prepped conv weights, bf16 hi/lo, layout [inst][tap][oc][ICP]
#define WC2_PER (9 * 64 * 40)
#define WC3_PER (9 * 32 * 72)
__device__ __nv_bfloat16 g_wc2h[4 * WC2_PER];
__device__ __nv_bfloat16 g_wc2l[4 * WC2_PER];
__device__ __nv_bfloat16 g_wc3h[2 * WC3_PER];
__device__ __nv_bfloat16 g_wc3l[2 * WC3_PER];

__device__ __forceinline__ float lrelu(float v) { return v >= 0.f ? v : 0.01f * v; }

__device__ __forceinline__ uint32_t smem_u32(const void* p) {
    uint32_t a;
    asm("{ .reg .u64 t; cvta.to.shared.u64 t, %1; cvt.u32.u64 %0, t; }" : "=r"(a) : "l"(p));
    return a;
}

// ================= mma.sync bf16 primitives (sm_80+ baseline ISA) ============
__device__ __forceinline__ void ldm_x4(uint32_t* r, uint32_t addr) {
    asm volatile("ldmatrix.sync.aligned.m8n8.x4.shared.b16 {%0,%1,%2,%3}, [%4];"
        : "=r"(r[0]), "=r"(r[1]), "=r"(r[2]), "=r"(r[3]) : "r"(addr));
}
__device__ __forceinline__ void mma_bf16(float* c, const uint32_t* a, const uint32_t* b) {
    asm volatile("mma.sync.aligned.m16n8k16.row.col.f32.bf16.bf16.f32 "
        "{%0,%1,%2,%3}, {%4,%5,%6,%7}, {%8,%9}, {%0,%1,%2,%3};"
        : "+f"(c[0]), "+f"(c[1]), "+f"(c[2]), "+f"(c[3])
        : "r"(a[0]), "r"(a[1]), "r"(a[2]), "r"(a[3]), "r"(b[0]), "r"(b[1]));
}

__device__ __forceinline__ uint32_t pack_bf(__nv_bfloat16 a, __nv_bfloat16 b) {
    return (uint32_t)__bfloat16_as_ushort(a) | ((uint32_t)__bfloat16_as_ushort(b) << 16);
}

__device__ __forceinline__ void cvt_store2(__nv_bfloat16* hi, __nv_bfloat16* lo,
                                           int off, float4 a)
{
    __nv_bfloat16 h0 = __float2bfloat16(a.x), h1 = __float2bfloat16(a.y);
    __nv_bfloat16 h2 = __float2bfloat16(a.z), h3 = __float2bfloat16(a.w);
    __nv_bfloat16 l0 = __float2bfloat16(a.x - __bfloat162float(h0));
    __nv_bfloat16 l1 = __float2bfloat16(a.y - __bfloat162float(h1));
    __nv_bfloat16 l2 = __float2bfloat16(a.z - __bfloat162float(h2));
    __nv_bfloat16 l3 = __float2bfloat16(a.w - __bfloat162float(h3));
    *(uint2*)&hi[off] = make_uint2(pack_bf(h0, h1), pack_bf(h2, h3));
    *(uint2*)&lo[off] = make_uint2(pack_bf(l0, l1), pack_bf(l2, l3));
}

#define TSTR 40   // FC smem row stride (elems): 80B row cycles all banks

// ---------------- prep: conv weights -> bf16 hi/lo, padded [tap][oc][ICP] ----
__global__ __launch_bounds__(256)
void prep_convw_kernel(const float* __restrict__ encW2, const float* __restrict__ decW2,
                       const float* __restrict__ encW3)
{
    const int T2 = 4 * WC2_PER;
    for (int i = blockIdx.x * 256 + threadIdx.x; i < T2; i += gridDim.x * 256) {
        int icp = i % 40;
        int t = i / 40;
        int oc = t % 64; t /= 64;
        int tap = t % 9; int inst = t / 9;
        float v = 0.f;
        if (icp < 32) {
            const float* s = (inst < 2) ? encW2 : decW2;
            v = s[((((size_t)(inst & 1) * 64 + oc) * 32 + icp) * 9) + tap];
        }
        __nv_bfloat16 h = __float2bfloat16(v);
        g_wc2h[i] = h;
        g_wc2l[i] = __float2bfloat16(v - __bfloat162float(h));
    }
    const int T3 = 2 * WC3_PER;
    for (int i = blockIdx.x * 256 + threadIdx.x; i < T3; i += gridDim.x * 256) {
        int icp = i % 72;
        int t = i / 72;
        int oc = t % 32; t /= 32;
        int tap = t % 9; int br = t / 9;
        float v = 0.f;
        if (icp < 64)
            v = encW3[((((size_t)br * 32 + oc) * 64 + icp) * 9) + tap];
        __nv_bfloat16 h = __float2bfloat16(v);
        g_wc3h[i] = h;
        g_wc3l[i] = __float2bfloat16(v - __bfloat162float(h));
    }
}

// ---------------- mega zero ---------------------------------------------------
__global__ __launch_bounds__(256)
void mega_zero_kernel()
{
    for (int i = blockIdx.x * 256 + threadIdx.x; i < 8 * 512 * 1024; i += gridDim.x * 256) {
        g_accbuf[i] = 0.f;
        if (i < 12 * 128) g_statp[i] = 0.f;
        if (i < 8 * 64)   g_cnt[i] = 0;
        if (i < 4)        g_red[i] = 0.f;
    }
}

// ---------------- FC GEMM: out = lrelu(A*B^T + bias), split-K + ticket -------
__global__ __launch_bounds__(256)
void fc_gemm_kernel(const float* __restrict__ A, const float* __restrict__ B,
                    const float* __restrict__ bias, float* __restrict__ acc,
                    int* __restrict__ cnt, float* __restrict__ outBuf,
                    int M, int Nn, int K, const float* __restrict__ statpIn)
{
    __shared__ __nv_bfloat16 sAhi[128 * TSTR], sAlo[128 * TSTR];
    __shared__ __nv_bfloat16 sBhi[128 * TSTR], sBlo[128 * TSTR];
    __shared__ float sstat[64];
    __shared__ int lastFlag;

    const int tid = threadIdx.x;
    const int wid = tid >> 5, lane = tid & 31;
    const int wm = (wid >> 2) * 64;
    const int wn = (wid & 3) * 32;

    const int m0 = blockIdx.x * 128, n0 = blockIdx.y * 128;
    const int kChunk = K / gridDim.z;
    const int k0 = blockIdx.z * kChunk;

    if (statpIn && tid < 32) {
        float m = statpIn[tid * 2] / NPF;
        float var = statpIn[tid * 2 + 1] / NPF - m * m;
        sstat[tid * 2] = m;
        sstat[tid * 2 + 1] = rsqrtf(var + 1e-5f);
    }
    __syncthreads();

    const uint32_t aHi = smem_u32(sAhi), aLo = smem_u32(sAlo);
    const uint32_t bHi = smem_u32(sBhi), bLo = smem_u32(sBlo);

    const uint32_t aRow = (uint32_t)(lane & 15);
    const uint32_t aColB = (uint32_t)((lane >> 4) * 16);
    const uint32_t bRow = (uint32_t)((lane & 7) + ((lane >> 4) & 1) * 8);
    const uint32_t bColB = (uint32_t)(((lane >> 3) & 1) * 16);

    float accr[4][4][4];
#pragma unroll
    for (int i = 0; i < 4; i++)
#pragma unroll
        for (int j = 0; j < 4; j++)
#pragma unroll
            for (int r = 0; r < 4; r++) accr[i][j][r] = 0.f;

    for (int kb = k0; kb < k0 + kChunk; kb += 32) {
        for (int idx = tid; idx < 1024; idx += 256) {
            int r = idx >> 3;
            int c = (idx & 7) << 2;
            float4 va = *(const float4*)&A[(size_t)(m0 + r) * K + kb + c];
            if (statpIn) {
                int ch = (kb + c) >> 10;
                float m = sstat[ch * 2], iv = sstat[ch * 2 + 1];
                va.x = lrelu((va.x - m) * iv);
                va.y = lrelu((va.y - m) * iv);
                va.z = lrelu((va.z - m) * iv);
                va.w = lrelu((va.w - m) * iv);
            }
            cvt_store2(sAhi, sAlo, r * TSTR + c, va);
            float4 vb = *(const float4*)&B[(size_t)(n0 + r) * K + kb + c];
            cvt_store2(sBhi, sBlo, r * TSTR + c, vb);
        }
        __syncthreads();

#pragma unroll
        for (int s = 0; s < 2; s++) {
            const uint32_t kofB = s * 32;
            uint32_t afh[4][4], afl[4][4];
#pragma unroll
            for (int mf = 0; mf < 4; mf++) {
                uint32_t off = (uint32_t)(wm + mf * 16 + aRow) * (TSTR * 2) + kofB + aColB;
                ldm_x4(afh[mf], aHi + off);
                ldm_x4(afl[mf], aLo + off);
            }
            uint32_t bfh[2][4], bfl[2][4];
#pragma unroll
            for (int h = 0; h < 2; h++) {
                uint32_t off = (uint32_t)(wn + h * 16 + bRow) * (TSTR * 2) + kofB + bColB;
                ldm_x4(bfh[h], bHi + off);
                ldm_x4(bfl[h], bLo + off);
            }
#pragma unroll
            for (int mf = 0; mf < 4; mf++)
#pragma unroll
                for (int nf = 0; nf < 4; nf++) {
                    const uint32_t* ph = &bfh[nf >> 1][(nf & 1) * 2];
                    const uint32_t* pl = &bfl[nf >> 1][(nf & 1) * 2];
                    mma_bf16(accr[mf][nf], afh[mf], ph);
                    mma_bf16(accr[mf][nf], afh[mf], pl);
                    mma_bf16(accr[mf][nf], afl[mf], ph);
                }
        }
        __syncthreads();
    }

    const int rbase = m0 + wm + (lane >> 2);
    const int cbase = n0 + wn + (lane & 3) * 2;
#pragma unroll
    for (int mf = 0; mf < 4; mf++)
#pragma unroll
        for (int nf = 0; nf < 4; nf++) {
            int row = rbase + mf * 16;
            int col = cbase + nf * 8;
            atomicAdd(&acc[(size_t)row * Nn + col],           accr[mf][nf][0]);
            atomicAdd(&acc[(size_t)row * Nn + col + 1],       accr[mf][nf][1]);
            atomicAdd(&acc[(size_t)(row + 8) * Nn + col],     accr[mf][nf][2]);
            atomicAdd(&acc[(size_t)(row + 8) * Nn + col + 1], accr[mf][nf][3]);
        }

    __threadfence();
    if (tid == 0) {
        int old = atomicAdd(&cnt[blockIdx.x * gridDim.y + blockIdx.y], 1);
        lastFlag = (old == (int)gridDim.z - 1);
    }
    __syncthreads();
    if (lastFlag) {
        __threadfence();
        const int r = tid >> 1;
        const int cb = (tid & 1) * 64;
#pragma unroll
        for (int j = 0; j < 16; j++) {
            int col = cb + j * 4;
            float4 v = *(const float4*)&acc[(size_t)(m0 + r) * Nn + n0 + col];
            float4 b = *(const float4*)&bias[n0 + col];
            v.x = lrelu(v.x + b.x); v.y = lrelu(v.y + b.y);
            v.z = lrelu(v.z + b.z); v.w = lrelu(v.w + b.w);
            *(float4*)&outBuf[(size_t)(m0 + r) * Nn + n0 + col] = v;
        }
    }
}

// ---------------- implicit-GEMM conv 3x3 SAME via mma.sync (bf16 hi/lo) ------
template<int IC, int OC>
__global__ __launch_bounds__(256, OC == 64 ? 4 : 3)
void conv_mma_kernel(const float* __restrict__ in,
                     const __nv_bfloat16* __restrict__ wHi,
                     const __nv_bfloat16* __restrict__ wLo,
                     const float* __restrict__ bias,
                     const float* __restrict__ statpIn, float* __restrict__ statpOut,
                     float* __restrict__ out)
{
    constexpr int ICP = (IC == 32) ? 40 : 72;
    constexpr int ISZ = 6 * 34 * ICP;
    constexpr int WSZ = OC * ICP;
    constexpr int KSTEPS = IC / 16;
    constexpr int LOG2IC = (IC == 32) ? 5 : 6;
    constexpr int WARPS_M = (OC == 64) ? 4 : 8;
    constexpr int WM = 128 / WARPS_M;
    constexpr int MFRAG = WM / 16;
    constexpr int NFRAG = 4;

    extern __shared__ char smraw[];
    __nv_bfloat16* sIhi = (__nv_bfloat16*)smraw;
    __nv_bfloat16* sIlo = sIhi + ISZ;
    __nv_bfloat16* sWh  = sIlo + ISZ;
    __nv_bfloat16* sWl  = sWh + WSZ;
    float* sstatIn  = (float*)(sWl + WSZ);
    float* sstatOut = sstatIn + 2 * IC;

    const int tid  = threadIdx.x;
    const int wid  = tid >> 5, lane = tid & 31;
    const int n    = blockIdx.x >> 3;
    const int tile = blockIdx.x & 7;
    const int r0   = tile * 4;

    if (tid < IC) {
        float m = statpIn[tid * 2] / NPF;
        float var = statpIn[tid * 2 + 1] / NPF - m * m;
        sstatIn[tid * 2] = m;
        sstatIn[tid * 2 + 1] = rsqrtf(var + 1e-5f);
    }
    for (int i = tid; i < 2 * OC; i += 256) sstatOut[i] = 0.f;
    __syncthreads();

    const float* src = in + (size_t)n * IC * SP;
    for (int i = tid; i < 6 * 34 * IC; i += 256) {
        int c = i % 34;
        int rest = i / 34;            // r*IC + ic
        int ic = rest & (IC - 1);
        int r = rest >> LOG2IC;
        int row = r0 - 1 + r, col = c - 1;
        float v = 0.f;
        if ((unsigned)row < 32u && (unsigned)col < 32u) {
            v = src[(size_t)ic * SP + row * 32 + col];
            v = (v - sstatIn[ic * 2]) * sstatIn[ic * 2 + 1];
            v = v >= 0.f ? v : 0.01f * v;
        }
        __nv_bfloat16 h = __float2bfloat16(v);
        int o = (r * 34 + c) * ICP + ic;
        sIhi[o] = h;
        sIlo[o] = __float2bfloat16(v - __bfloat162float(h));
    }

    const int wm = (OC == 64) ? ((wid >> 1) * 32) : (wid * 16);
    const int wn = (OC == 64) ? ((wid & 1) * 32) : 0;

    uint32_t aBase[MFRAG];
    {
        int pixl = wm + (lane & 15);
#pragma unroll
        for (int mf = 0; mf < MFRAG; mf++) {
            int p = pixl + mf * 16;
            int plane = (p >> 5) * 34 + (p & 31);
            aBase[mf] = (uint32_t)(plane * ICP * 2) + ((lane & 16) ? 16u : 0u);
        }
    }
    const uint32_t aHiB = smem_u32(sIhi), aLoB = smem_u32(sIlo);
    const uint32_t wHiB = smem_u32(sWh),  wLoB = smem_u32(sWl);
    const uint32_t bRow  = (uint32_t)((lane & 7) + ((lane >> 4) & 1) * 8);
    const uint32_t bColB = (uint32_t)((((lane >> 3) & 1) * 8) * 2);

    // loop-invariant weight fragment offsets (hoisted)
    uint32_t wOff[2];
#pragma unroll
    for (int h = 0; h < 2; h++)
        wOff[h] = (uint32_t)((wn + h * 16 + bRow) * ICP) * 2 + bColB;

    float acc[MFRAG][NFRAG][4];
#pragma unroll
    for (int mf = 0; mf < MFRAG; mf++)
#pragma unroll
        for (int nf = 0; nf < NFRAG; nf++) {
            float b0 = bias[wn + nf * 8 + (lane & 3) * 2];
            float b1 = bias[wn + nf * 8 + (lane & 3) * 2 + 1];
            acc[mf][nf][0] = b0; acc[mf][nf][1] = b1;
            acc[mf][nf][2] = b0; acc[mf][nf][3] = b1;
        }

    for (int tap = 0; tap < 9; tap++) {
        __syncthreads();
        {
            const uint4* gh = (const uint4*)(wHi + tap * WSZ);
            const uint4* gl = (const uint4*)(wLo + tap * WSZ);
            uint4* dh = (uint4*)sWh;
            uint4* dl = (uint4*)sWl;
            for (int i = tid; i < WSZ / 8; i += 256) { dh[i] = gh[i]; dl[i] = gl[i]; }
        }
        __syncthreads();

        const uint32_t tapOff = (uint32_t)((((tap / 3) * 34) + (tap % 3)) * ICP * 2);
#pragma unroll
        for (int ks = 0; ks < KSTEPS; ks++) {
            const uint32_t kOff = (uint32_t)(ks * 32);
            uint32_t afh[MFRAG][4], afl[MFRAG][4];
#pragma unroll
            for (int mf = 0; mf < MFRAG; mf++) {
                uint32_t ad = aBase[mf] + tapOff + kOff;
                ldm_x4(afh[mf], aHiB + ad);
                ldm_x4(afl[mf], aLoB + ad);
            }
            uint32_t bfh[2][4], bfl[2][4];
#pragma unroll
            for (int h = 0; h < 2; h++) {
                uint32_t od = wOff[h] + kOff;
                ldm_x4(bfh[h], wHiB + od);
                ldm_x4(bfl[h], wLoB + od);
            }
#pragma unroll
            for (int mf = 0; mf < MFRAG; mf++)
#pragma unroll
                for (int nf = 0; nf < NFRAG; nf++) {
                    const uint32_t* ph = &bfh[nf >> 1][(nf & 1) * 2];
                    const uint32_t* pl = &bfl[nf >> 1][(nf & 1) * 2];
                    mma_bf16(acc[mf][nf], afh[mf], ph);
                    mma_bf16(acc[mf][nf], afh[mf], pl);
                    mma_bf16(acc[mf][nf], afl[mf], ph);
                }
        }
    }

#pragma unroll
    for (int nf = 0; nf < NFRAG; nf++) {
        float s0 = 0.f, q0 = 0.f, s1 = 0.f, q1 = 0.f;
#pragma unroll
        for (int mf = 0; mf < MFRAG; mf++) {
            float v0 = acc[mf][nf][0], v1 = acc[mf][nf][1];
            float v2 = acc[mf][nf][2], v3 = acc[mf][nf][3];
            s0 += v0 + v2; q0 += v0 * v0 + v2 * v2;
            s1 += v1 + v3; q1 += v1 * v1 + v3 * v3;
        }
#pragma unroll
        for (int off = 4; off < 32; off <<= 1) {
            s0 += __shfl_xor_sync(~0u, s0, off);
            q0 += __shfl_xor_sync(~0u, q0, off);
            s1 += __shfl_xor_sync(~0u, s1, off);
            q1 += __shfl_xor_sync(~0u, q1, off);
        }
        if (lane < 4) {
            int c0 = wn + nf * 8 + lane * 2;
            atomicAdd(&sstatOut[c0 * 2],     s0);
            atomicAdd(&sstatOut[c0 * 2 + 1], q0);
            atomicAdd(&sstatOut[(c0 + 1) * 2],     s1);
            atomicAdd(&sstatOut[(c0 + 1) * 2 + 1], q1);
        }
    }

    float* dst = out + (size_t)n * OC * SP + tile * 128;
    const int prow  = lane >> 2;
    const int pcol0 = (lane & 3) * 2;
#pragma unroll
    for (int mf = 0; mf < MFRAG; mf++)
#pragma unroll
        for (int nf = 0; nf < NFRAG; nf++) {
            int p0 = wm + mf * 16 + prow;
            int oc = wn + nf * 8 + pcol0;
            dst[(size_t)oc * SP + p0]           = acc[mf][nf][0];
            dst[(size_t)(oc + 1) * SP + p0]     = acc[mf][nf][1];
            dst[(size_t)oc * SP + p0 + 8]       = acc[mf][nf][2];
            dst[(size_t)(oc + 1) * SP + p0 + 8] = acc[mf][nf][3];
        }

    __syncthreads();
    for (int i = tid; i < 2 * OC; i += 256)
        atomicAdd(&statpOut[i], sstatOut[i]);
}

// ---------------- direct conv (1->32 layers), fused in-BN + out-stats --------
template<int IC, int OCT>
__global__ __launch_bounds__(256)
void conv_bn_kernel(const float* __restrict__ in, const float* __restrict__ w,
                    const float* __restrict__ bias,
                    const float* __restrict__ statpIn, float* __restrict__ statpOut,
                    float* __restrict__ out, int OC)
{
    __shared__ __align__(16) float ws[IC * 9 * OCT];
    __shared__ float plane[2][34 * 35];
    __shared__ float sstatIn[2 * IC];
    __shared__ float so[2 * OCT];
    const int tid = threadIdx.x;
    const int n   = blockIdx.x;
    const int ocb = blockIdx.y * OCT;

    if (statpIn && tid < IC) {
        float m = statpIn[tid * 2] / NPF;
        float var = statpIn[tid * 2 + 1] / NPF - m * m;
        sstatIn[tid * 2] = m;
        sstatIn[tid * 2 + 1] = rsqrtf(var + 1e-5f);
    }
    if (tid < 2 * OCT) so[tid] = 0.f;

    for (int idx = tid; idx < IC * 9 * OCT; idx += 256) {
        int oc = idx % OCT;
        int rest = idx / OCT;
        int ic = rest / 9, t = rest % 9;
        ws[idx] = w[((size_t)(ocb + oc) * IC + ic) * 9 + t];
    }

    float acc[OCT][4];
#pragma unroll
    for (int oc = 0; oc < OCT; oc++) {
        float b = bias[ocb + oc];
#pragma unroll
        for (int p = 0; p < 4; p++) acc[oc][p] = b;
    }

    const int row  = tid >> 3;
    const int col0 = (tid & 7) * 4;
    const float* src = in + (size_t)n * IC * SP;

    auto loadPlane = [&](int ic) {
        float m = 0.f, iv = 1.f;
        if (statpIn) { m = sstatIn[ic * 2]; iv = sstatIn[ic * 2 + 1]; }
        const float* s = src + (size_t)ic * SP;
        float* dstp = plane[ic & 1];
        for (int p = tid; p < 34 * 34; p += 256) {
            int py = p / 34 - 1, px = p % 34 - 1;
            float v = 0.f;
            if ((unsigned)py < 32u && (unsigned)px < 32u) {
                v = s[py * 32 + px];
                if (statpIn) { v = (v - m) * iv; v = v >= 0.f ? v : 0.01f * v; }
            }
            dstp[(p / 34) * 35 + (p % 34)] = v;
        }
    };

    __syncthreads();
    loadPlane(0);
    __syncthreads();

    for (int ic = 0; ic < IC; ic++) {
        if (ic + 1 < IC) loadPlane(ic + 1);

        const float* pl = plane[ic & 1];
        float v[3][6];
#pragma unroll
        for (int dy = 0; dy < 3; dy++)
#pragma unroll
            for (int dx = 0; dx < 6; dx++)
                v[dy][dx] = pl[(row + dy) * 35 + col0 + dx];

        const float* wp = &ws[ic * 9 * OCT];
#pragma unroll
        for (int t = 0; t < 9; t++) {
            const int ky = t / 3, kx = t % 3;
            if constexpr (OCT == 8) {
                float4 w0 = *(const float4*)&wp[t * 8];
                float4 w1 = *(const float4*)&wp[t * 8 + 4];
#pragma unroll
                for (int p = 0; p < 4; p++) {
                    float vv = v[ky][kx + p];
                    acc[0][p] += vv * w0.x; acc[1][p] += vv * w0.y;
                    acc[2][p] += vv * w0.z; acc[3][p] += vv * w0.w;
                    acc[4][p] += vv * w1.x; acc[5][p] += vv * w1.y;
                    acc[6][p] += vv * w1.z; acc[7][p] += vv * w1.w;
                }
            } else {
                float wv = wp[t];
#pragma unroll
                for (int p = 0; p < 4; p++)
                    acc[0][p] += v[ky][kx + p] * wv;
            }
        }
        __syncthreads();
    }

#pragma unroll
    for (int oc = 0; oc < OCT; oc++) {
        float4 o = make_float4(acc[oc][0], acc[oc][1], acc[oc][2], acc[oc][3]);
        *(float4*)&out[((size_t)n * OC + ocb + oc) * SP + row * 32 + col0] = o;
        float s = acc[oc][0] + acc[oc][1] + acc[oc][2] + acc[oc][3];
        float q = acc[oc][0] * acc[oc][0] + acc[oc][1] * acc[oc][1]
                + acc[oc][2] * acc[oc][2] + acc[oc][3] * acc[oc][3];
#pragma unroll
        for (int off = 16; off > 0; off >>= 1) {
            s += __shfl_xor_sync(~0u, s, off);
            q += __shfl_xor_sync(~0u, q, off);
        }
        if ((tid & 31) == 0) {
            atomicAdd(&so[oc * 2], s);
            atomicAdd(&so[oc * 2 + 1], q);
        }
    }
    __syncthreads();
    if (tid < 2 * OCT)
        atomicAdd(&statpOut[ocb * 2 + tid], so[tid]);
}

// ---------------- decoder final conv 64->1, tiled (grid NB x 8) --------------
__global__ __launch_bounds__(256)
void dec3_kernel(const float* __restrict__ in, const float* __restrict__ w,
                 const float* __restrict__ bias,
                 const float* __restrict__ statpIn, float* __restrict__ statpOut,
                 float* __restrict__ out)
{
    __shared__ float sw[64 * 9];
    __shared__ float halo[2][6 * 35];
    __shared__ float sstatIn[128];
    __shared__ float so[2];

    const int tid  = threadIdx.x;
    const int n    = blockIdx.x;
    const int tile = blockIdx.y;
    const int r0   = tile * 4;
    const int pixel = tid >> 1;
    const int half  = tid & 1;
    const int prow  = pixel >> 5;
    const int pcol  = pixel & 31;

    if (tid < 64) {
        float m = statpIn[tid * 2] / NPF;
        float var = statpIn[tid * 2 + 1] / NPF - m * m;
        sstatIn[tid * 2] = m;
        sstatIn[tid * 2 + 1] = rsqrtf(var + 1e-5f);
    }
    if (tid < 2) so[tid] = 0.f;
    for (int i = tid; i < 64 * 9; i += 256) sw[i] = w[i];

    const float* src = in + (size_t)n * 64 * SP;

    auto loadHalo = [&](int ic) {
        float m = sstatIn[ic * 2], iv = sstatIn[ic * 2 + 1];
        const float* s = src + (size_t)ic * SP;
        float* d = halo[ic & 1];
        for (int p = tid; p < 6 * 34; p += 256) {
            int r = p / 34, c = p % 34;
            int row = r0 - 1 + r, col = c - 1;
            float v = 0.f;
            if ((unsigned)row < 32u && (unsigned)col < 32u) {
                v = s[row * 32 + col];
                v = (v - m) * iv;
                v = v >= 0.f ? v : 0.01f * v;
            }
            d[r * 35 + c] = v;
        }
    };

    __syncthreads();
    loadHalo(0);
    __syncthreads();

    float acc = 0.f;
    for (int ic = 0; ic < 64; ic++) {
        if (ic + 1 < 64) loadHalo(ic + 1);
        if ((ic >> 5) == half) {
            const float* pl = halo[ic & 1];
            const float* wp = &sw[ic * 9];
#pragma unroll
            for (int t = 0; t < 9; t++)
                acc += pl[(prow + t / 3) * 35 + pcol + t % 3] * wp[t];
        }
        __syncthreads();
    }

    float other = __shfl_xor_sync(~0u, acc, 1);
    float v = acc + other + bias[0];
    if (half == 0)
        out[(size_t)n * SP + tile * 128 + pixel] = v;

    float s = (half == 0) ? v : 0.f;
    float q = (half == 0) ? v * v : 0.f;
#pragma unroll
    for (int off = 16; off > 0; off >>= 1) {
        s += __shfl_xor_sync(~0u, s, off);
        q += __shfl_xor_sync(~0u, q, off);
    }
    if ((tid & 31) == 0) {
        atomicAdd(&so[0], s);
        atomicAdd(&so[1], q);
    }
    __syncthreads();
    if (tid < 2)
        atomicAdd(&statpOut[tid], so[tid]);
}

// ---------------- PoE (parallel: 8 threads per latent) -----------------------
__global__ __launch_bounds__(256)
void poe_kernel(const float* __restrict__ smu, const float* __restrict__ slv,
                float* __restrict__ gmu, float* __restrict__ glv)
{
    const int tid = threadIdx.x;
    const int l   = blockIdx.x * 32 + (tid >> 3);
    const int sub = tid & 7;
    float s1 = 0.f, s2 = 0.f;
    for (int n = sub * 64; n < (sub + 1) * 64; n++) {
        float lv = slv[n * LAT + l];
        float pr = expf(-lv);
        s1 += pr;
        s2 += smu[n * LAT + l] * pr;
    }
#pragma unroll
    for (int off = 4; off > 0; off >>= 1) {
        s1 += __shfl_xor_sync(~0u, s1, off);
        s2 += __shfl_xor_sync(~0u, s2, off);
    }
    if (sub == 0) {
        float gv = 1.f / s1;
        gmu[l] = s2 * gv;
        glv[l] = logf(gv);
    }
}

__global__ void reparam_c_kernel(const float* __restrict__ eps, const float* __restrict__ lv,
                                 const float* __restrict__ mu, float* __restrict__ z)
{
    int i = blockIdx.x * 256 + threadIdx.x;
    if (i >= NB * LAT) return;
    z[i] = eps[i] * expf(0.5f * lv[i]) + mu[i];
}

__global__ void reparam_s_kernel(const float* __restrict__ eps, const float* __restrict__ glv,
                                 const float* __restrict__ gmu, float* __restrict__ z)
{
    int i = blockIdx.x * 256 + threadIdx.x;
    if (i >= NB * LAT) return;
    int l = i & (LAT - 1);
    z[i] = eps[i] * expf(0.5f * glv[l]) + gmu[l];
}

// ---------------- KL reductions ----------------------------------------------
__global__ __launch_bounds__(256)
void kl_class_kernel(const float* __restrict__ mu, const float* __restrict__ lv,
                     float* __restrict__ red)
{
    float a = 0.f, b = 0.f, c = 0.f;
    for (int i = blockIdx.x * 256 + threadIdx.x; i < NB * LAT; i += gridDim.x * 256) {
        float l = lv[i], m = mu[i];
        a += 1.f + l;
        b += m * m;
        c += expf(2.f * l);
    }
    __shared__ float sh0[256], sh1[256], sh2[256];
    int tid = threadIdx.x;
    sh0[tid] = a; sh1[tid] = b; sh2[tid] = c;
    __syncthreads();
    for (int o = 128; o > 0; o >>= 1) {
        if (tid < o) { sh0[tid] += sh0[tid + o]; sh1[tid] += sh1[tid + o]; sh2[tid] += sh2[tid + o]; }
        __syncthreads();
    }
    if (tid == 0) {
        atomicAdd(&red[0], sh0[0]);
        atomicAdd(&red[1], sh1[0]);
        atomicAdd(&red[2], sh2[0]);
    }
}

__global__ __launch_bounds__(256)
void kl_final_kernel(const float* __restrict__ gmu, const float* __restrict__ glv,
                     const float* __restrict__ red, float* __restrict__ kl)
{
    float a = 0.f, b = 0.f, c = 0.f;
    int tid = threadIdx.x;
    for (int l = tid; l < LAT; l += 256) {
        float g = glv[l], m = gmu[l];
        a += 1.f + g;
        b += m * m;
        c += expf(2.f * g);
    }
    __shared__ float sh0[256], sh1[256], sh2[256];
    sh0[tid] = a; sh1[tid] = b; sh2[tid] = c;
    __syncthreads();
    for (int o = 128; o > 0; o >>= 1) {
        if (tid < o) { sh0[tid] += sh0[tid + o]; sh1[tid] += sh1[tid + o]; sh2[tid] += sh2[tid + o]; }
        __syncthreads();
    }
    if (tid == 0) {
        kl[0] = -0.5f * red[0] + 0.5f * (red[1] + red[2]);
        kl[1] = -0.5f * sh0[0] + 0.5f * (sh1[0] + sh2[0]);
    }
}

// ---------------- final loss + output (applies decoder-final BNs) ------------
__global__ __launch_bounds__(256)
void final_kernel(const float* __restrict__ x, const float* __restrict__ outc,
                  const float* __restrict__ outs, const float* __restrict__ kl,
                  const float* __restrict__ spC, const float* __restrict__ spS,
                  float* __restrict__ dout)
{
    int i = blockIdx.x * 256 + threadIdx.x;
    if (i >= NB * SP) return;
    float mc = spC[0] / NPF, vc = spC[1] / NPF - mc * mc;
    float ivc = rsqrtf(vc + 1e-5f);
    float ms = spS[0] / NPF, vs = spS[1] / NPF - ms * ms;
    float ivs = rsqrtf(vs + 1e-5f);
    float oc = lrelu((outc[i] - mc) * ivc);
    float os = fmaxf((outs[i] - ms) * ivs, 0.f);
    float o  = oc * os;
    float d  = expf(x[i]) - expf(o);
    dout[i]           = -kl[0] + kl[1] + d * d;
    dout[NB * SP + i] = o;
}

// ---------------- host orchestration -----------------------------------------
#define SMEM_C2 ((2 * 8160 + 2 * 2560) * 2 + (2 * 32 + 2 * 64) * 4)    // 43648
#define SMEM_C3 ((2 * 14688 + 2 * 2304) * 2 + (2 * 64 + 2 * 32) * 4)   // 68736

static void run_encode(const float* xin,
                       const float* cw1, const float* cb1,
                       const __nv_bfloat16* w2h, const __nv_bfloat16* w2l, const float* cb2,
                       const __nv_bfloat16* w3h, const __nv_bfloat16* w3l, const float* cb3,
                       const float* W1mu, const float* b1mu,
                       const float* W2mu, const float* b2mu,
                       const float* W1va, const float* b1va,
                       const float* W2va, const float* b2va,
                       float* mu_out, float* lv_out,
                       float* bufA, float* bufB, float* statp, int sBase,
                       float* accb, int* cnt, int accBase, float* hid)
{
    float* s0 = statp + (sBase + 0) * 128;
    float* s1 = statp + (sBase + 1) * 128;
    float* s2 = statp + (sBase + 2) * 128;
    float* a0 = accb + (size_t)(accBase + 0) * 512 * 1024;
    float* a1 = accb + (size_t)(accBase + 1) * 512 * 1024;
    float* a2 = accb + (size_t)(accBase + 2) * 512 * 1024;
    float* a3 = accb + (size_t)(accBase + 3) * 512 * 1024;
    int* c0 = cnt + (accBase + 0) * 64;
    int* c1 = cnt + (accBase + 1) * 64;
    int* c2 = cnt + (accBase + 2) * 64;
    int* c3 = cnt + (accBase + 3) * 64;

    conv_bn_kernel<1, 8><<<dim3(NB, 4), 256>>>(xin, cw1, cb1, nullptr, s0, bufA, 32);
    conv_mma_kernel<32, 64><<<NB * 8, 256, SMEM_C2>>>(bufA, w2h, w2l, cb2, s0, s1, bufB);
    conv_mma_kernel<64, 32><<<NB * 8, 256, SMEM_C3>>>(bufB, w3h, w3l, cb3, s1, s2, bufA);

    fc_gemm_kernel<<<dim3(4, 4, 16), 256>>>(bufA, W1mu, b1mu, a0, c0, hid, NB, HID, FDIM, s2);
    fc_gemm_kernel<<<dim3(4, 8, 4), 256>>>(hid, W2mu, b2mu, a1, c1, mu_out, NB, LAT, HID, nullptr);
    fc_gemm_kernel<<<dim3(4, 4, 16), 256>>>(bufA, W1va, b1va, a2, c2, hid, NB, HID, FDIM, s2);
    fc_gemm_kernel<<<dim3(4, 8, 4), 256>>>(hid, W2va, b2va, a3, c3, lv_out, NB, LAT, HID, nullptr);
}

static void run_decode(const float* z,
                       const float* cw1, const float* cb1,
                       const __nv_bfloat16* w2h, const __nv_bfloat16* w2l, const float* cb2,
                       const float* cw3, const float* cb3,
                       float* outRaw, float* bufA, float* bufB,
                       float* statp, int sBase)
{
    float* s0 = statp + (sBase + 0) * 128;
    float* s1 = statp + (sBase + 1) * 128;
    float* s2 = statp + (sBase + 2) * 128;
    conv_bn_kernel<1, 8><<<dim3(NB, 4), 256>>>(z, cw1, cb1, nullptr, s0, bufA, 32);
    conv_mma_kernel<32, 64><<<NB * 8, 256, SMEM_C2>>>(bufA, w2h, w2l, cb2, s0, s1, bufB);
    dec3_kernel<<<dim3(NB, 8), 256>>>(bufB, cw3, cb3, s1, s2, outRaw);
}

extern "C" void kernel_launch(void* const* d_in, const int* in_sizes, int n_in,
                              void* d_out, int out_size)
{
    (void)in_sizes; (void)n_in; (void)out_size;

    const float* x       = (const float*)d_in[0];
    const float* eps_c   = (const float*)d_in[1];
    const float* eps_s   = (const float*)d_in[2];
    const float* enc_cw1 = (const float*)d_in[3];
    const float* enc_cb1 = (const float*)d_in[4];
    const float* enc_cw2 = (const float*)d_in[5];
    const float* enc_cb2 = (const float*)d_in[6];
    const float* enc_cw3 = (const float*)d_in[7];
    const float* enc_cb3 = (const float*)d_in[8];
    const float* enc_muW1 = (const float*)d_in[9];
    const float* enc_muB1 = (const float*)d_in[10];
    const float* enc_muW2 = (const float*)d_in[11];
    const float* enc_muB2 = (const float*)d_in[12];
    const float* enc_vaW1 = (const float*)d_in[13];
    const float* enc_vaB1 = (const float*)d_in[14];
    const float* enc_vaW2 = (const float*)d_in[15];
    const float* enc_vaB2 = (const float*)d_in[16];
    const float* dec_cw1 = (const float*)d_in[17];
    const float* dec_cb1 = (const float*)d_in[18];
    const float* dec_cw2 = (const float*)d_in[19];
    const float* dec_cb2 = (const float*)d_in[20];
    const float* dec_cw3 = (const float*)d_in[21];
    const float* dec_cb3 = (const float*)d_in[22];

    cudaFuncSetAttribute(conv_mma_kernel<32, 64>,
                         cudaFuncAttributeMaxDynamicSharedMemorySize, SMEM_C2);
    cudaFuncSetAttribute(conv_mma_kernel<64, 32>,
                         cudaFuncAttributeMaxDynamicSharedMemorySize, SMEM_C3);

    float *bufA, *bufB, *hid, *cmu, *clv, *smu, *slv, *zc, *zs;
    float *outc, *outs, *gmu, *glv, *statp, *accb, *red, *kl;
    int* cnt;
    __nv_bfloat16 *wc2h, *wc2l, *wc3h, *wc3l;
    cudaGetSymbolAddress((void**)&bufA,  g_bufA);
    cudaGetSymbolAddress((void**)&bufB,  g_bufB);
    cudaGetSymbolAddress((void**)&hid,   g_hid);
    cudaGetSymbolAddress((void**)&cmu,   g_cmu);
    cudaGetSymbolAddress((void**)&clv,   g_clv);
    cudaGetSymbolAddress((void**)&smu,   g_smu);
    cudaGetSymbolAddress((void**)&slv,   g_slv);
    cudaGetSymbolAddress((void**)&zc,    g_zc);
    cudaGetSymbolAddress((void**)&zs,    g_zs);
    cudaGetSymbolAddress((void**)&outc,  g_outc);
    cudaGetSymbolAddress((void**)&outs,  g_outs);
    cudaGetSymbolAddress((void**)&gmu,   g_gmu);
    cudaGetSymbolAddress((void**)&glv,   g_glv);
    cudaGetSymbolAddress((void**)&statp, g_statp);
    cudaGetSymbolAddress((void**)&accb,  g_accbuf);
    cudaGetSymbolAddress((void**)&cnt,   g_cnt);
    cudaGetSymbolAddress((void**)&red,   g_red);
    cudaGetSymbolAddress((void**)&kl,    g_kl);
    cudaGetSymbolAddress((void**)&wc2h,  g_wc2h);
    cudaGetSymbolAddress((void**)&wc2l,  g_wc2l);
    cudaGetSymbolAddress((void**)&wc3h,  g_wc3h);
    cudaGetSymbolAddress((void**)&wc3l,  g_wc3l);

    mega_zero_kernel<<<2048, 256>>>();
    prep_convw_kernel<<<256, 256>>>(enc_cw2, dec_cw2, enc_cw3);

    run_encode(x,
               enc_cw1, enc_cb1,
               wc2h + 0 * WC2_PER, wc2l + 0 * WC2_PER, enc_cb2,
               wc3h + 0 * WC3_PER, wc3l + 0 * WC3_PER, enc_cb3,
               enc_muW1, enc_muB1, enc_muW2, enc_muB2,
               enc_vaW1, enc_vaB1, enc_vaW2, enc_vaB2,
               cmu, clv, bufA, bufB, statp, 0, accb, cnt, 0, hid);

    run_encode(x,
               enc_cw1 + 32 * 9, enc_cb1 + 32,
               wc2h + 1 * WC2_PER, wc2l + 1 * WC2_PER, enc_cb2 + 64,
               wc3h + 1 * WC3_PER, wc3l + 1 * WC3_PER, enc_cb3 + 32,
               enc_muW1 + (size_t)HID * FDIM, enc_muB1 + HID,
               enc_muW2 + (size_t)LAT * HID,  enc_muB2 + LAT,
               enc_vaW1 + (size_t)HID * FDIM, enc_vaB1 + HID,
               enc_vaW2 + (size_t)LAT * HID,  enc_vaB2 + LAT,
               smu, slv, bufA, bufB, statp, 3, accb, cnt, 4, hid);

    poe_kernel<<<32, 256>>>(smu, slv, gmu, glv);

    reparam_c_kernel<<<(NB * LAT) / 256, 256>>>(eps_c, clv, cmu, zc);
    reparam_s_kernel<<<(NB * LAT) / 256, 256>>>(eps_s, glv, gmu, zs);

    run_decode(zc, dec_cw1, dec_cb1,
               wc2h + 2 * WC2_PER, wc2l + 2 * WC2_PER, dec_cb2,
               dec_cw3, dec_cb3,
               outc, bufA, bufB, statp, 6);
    run_decode(zs, dec_cw1 + 32 * 9, dec_cb1 + 32,
               wc2h + 3 * WC2_PER, wc2l + 3 * WC2_PER, dec_cb2 + 64,
               dec_cw3 + 64 * 9, dec_cb3 + 1,
               outs, bufA, bufB, statp, 9);

    kl_class_kernel<<<256, 256>>>(cmu, clv, red);
    kl_final_kernel<<<1, 256>>>(gmu, glv, red, kl);

    final_kernel<<<(NB * SP) / 256, 256>>>(x, outc, outs, kl,
                                           statp + 8 * 128, statp + 11 * 128,
                                           (float*)d_out);
}